// round 6
// baseline (speedup 1.0000x reference)
#include <cuda_runtime.h>
#include <math_constants.h>

// CrossEntropyLoss: mean over rows of  sum_c -log_softmax(pred)[n,c] * target[n,c]
//   = mean_n [ lse_n * (sum_c t) - sum_c t*x ],  lse_n = max_n + log(sum exp(x - max_n))
// Persistent-grid single pass (~2.1 GB read once) + 1-thread finalize kernel.

#define N_ROWS   8192
#define C_COLS   32000
#define C_VEC    (C_COLS / 4)   // 8000 float4 per row per tensor
#define THREADS  256
#define NWARPS   (THREADS / 32)
#define GRID     1184           // 148 SMs x 8 CTAs/SM (occupancy limit at 8 warps/CTA)

// Global accumulator (no cudaMalloc allowed anywhere). Reset by finalize
// kernel each launch -> graph-replay-safe.
__device__ float g_sum = 0.0f;

__global__ void __launch_bounds__(THREADS)
ce_row_kernel(const float* __restrict__ pred, const float* __restrict__ tgt)
{
    const int tid = threadIdx.x;
    const int wid = tid >> 5;
    const int lid = tid & 31;

    __shared__ float sh_m[NWARPS], sh_s[NWARPS], sh_d[NWARPS], sh_t[NWARPS];

    float cta_sum = 0.0f;  // only meaningful on tid==0

    for (int row = blockIdx.x; row < N_ROWS; row += GRID) {
        const float4* __restrict__ p = reinterpret_cast<const float4*>(pred + (size_t)row * C_COLS);
        const float4* __restrict__ t = reinterpret_cast<const float4*>(tgt  + (size_t)row * C_COLS);

        // Online logsumexp state + linear accumulators
        float m    = -CUDART_INF_F;  // running max
        float s    = 0.0f;           // sum exp(x - m)
        float dacc = 0.0f;           // sum t*x
        float tacc = 0.0f;           // sum t

        // Unroll 4 -> up to 8 front-batched LDG.128 per group (MLP depth).
        #pragma unroll 4
        for (int i = tid; i < C_VEC; i += THREADS) {
            float4 x = p[i];
            float4 y = t[i];

            dacc = fmaf(x.x, y.x, dacc);
            dacc = fmaf(x.y, y.y, dacc);
            dacc = fmaf(x.z, y.z, dacc);
            dacc = fmaf(x.w, y.w, dacc);
            tacc += (y.x + y.y) + (y.z + y.w);

            // local max of the 4; rescale only when it beats the running max
            // (short predicated arm, ~1 exp per element total)
            float lm = fmaxf(fmaxf(x.x, x.y), fmaxf(x.z, x.w));
            if (lm > m) {
                s *= __expf(m - lm);   // first hit: s==0, __expf(-inf)=0 -> stays 0
                m = lm;
            }
            s += __expf(x.x - m) + __expf(x.y - m)
               + __expf(x.z - m) + __expf(x.w - m);
        }

        // ---- warp reduction of (m, s, dacc, tacc) ----
        #pragma unroll
        for (int off = 16; off > 0; off >>= 1) {
            float m2 = __shfl_xor_sync(0xFFFFFFFFu, m, off);
            float s2 = __shfl_xor_sync(0xFFFFFFFFu, s, off);
            float nm = fmaxf(m, m2);
            s = s * __expf(m - nm) + s2 * __expf(m2 - nm);
            m = nm;
            dacc += __shfl_xor_sync(0xFFFFFFFFu, dacc, off);
            tacc += __shfl_xor_sync(0xFFFFFFFFu, tacc, off);
        }

        // ---- block reduction across warps ----
        if (lid == 0) {
            sh_m[wid] = m; sh_s[wid] = s; sh_d[wid] = dacc; sh_t[wid] = tacc;
        }
        __syncthreads();

        if (tid == 0) {
            float M = sh_m[0], S = sh_s[0], D = sh_d[0], T = sh_t[0];
            #pragma unroll
            for (int w = 1; w < NWARPS; w++) {
                float m2 = sh_m[w], s2 = sh_s[w];
                float nm = fmaxf(M, m2);
                S = S * __expf(M - nm) + s2 * __expf(m2 - nm);
                M = nm;
                D += sh_d[w];
                T += sh_t[w];
            }
            float lse = M + __logf(S);
            cta_sum += lse * T - D;
        }
        __syncthreads();   // protect sh_* reuse on next row iteration
    }

    // one global atomic per CTA, no fence (kernel boundary orders it)
    if (tid == 0)
        atomicAdd(&g_sum, cta_sum);
}

__global__ void ce_finalize_kernel(float* __restrict__ out)
{
    out[0] = g_sum * (1.0f / (float)N_ROWS);
    g_sum  = 0.0f;   // reset for next graph replay
}

extern "C" void kernel_launch(void* const* d_in, const int* in_sizes, int n_in,
                              void* d_out, int out_size)
{
    const float* pred = (const float*)d_in[0];
    const float* tgt  = (const float*)d_in[1];
    float* out = (float*)d_out;

    ce_row_kernel<<<GRID, THREADS>>>(pred, tgt);
    ce_finalize_kernel<<<1, 1>>>(out);
}

// round 7
// speedup vs baseline: 1.2060x; 1.2060x over previous
#include <cuda_runtime.h>
#include <math_constants.h>

// CrossEntropyLoss: mean over rows of  sum_c -log_softmax(pred)[n,c] * target[n,c]
//   = mean_n [ lse_n * (sum_c t) - sum_c t*x ],  lse_n = max_n + log(sum exp(x - max_n))
// R4 row kernel shape (best measured: 7.4 TB/s) + atomic tail + 1-thread finalize.

#define N_ROWS   8192
#define C_COLS   32000
#define C_VEC    (C_COLS / 4)   // 8000 float4 per row per tensor
#define THREADS  256
#define NWARPS   (THREADS / 32)

// Global accumulator (no cudaMalloc allowed anywhere). Reset by finalize
// kernel every launch -> graph-replay-safe.
__device__ float g_sum = 0.0f;

__global__ void __launch_bounds__(THREADS)
ce_row_kernel(const float* __restrict__ pred, const float* __restrict__ tgt)
{
    const int row = blockIdx.x;
    const float4* __restrict__ p = reinterpret_cast<const float4*>(pred + (size_t)row * C_COLS);
    const float4* __restrict__ t = reinterpret_cast<const float4*>(tgt  + (size_t)row * C_COLS);
    const int tid = threadIdx.x;

    // Online logsumexp state + linear accumulators
    float m    = -CUDART_INF_F;  // running max
    float s    = 0.0f;           // sum exp(x - m)
    float dacc = 0.0f;           // sum t*x
    float tacc = 0.0f;           // sum t

    // 8000 vec4 / 256 threads = 31.25 iters/thread. Unroll 4 -> up to 8
    // front-batched LDG.128 per group (MLP depth). Default .ca loads
    // (measured faster than __ldcs on this stream).
    #pragma unroll 4
    for (int i = tid; i < C_VEC; i += THREADS) {
        float4 x = p[i];
        float4 y = t[i];

        dacc = fmaf(x.x, y.x, dacc);
        dacc = fmaf(x.y, y.y, dacc);
        dacc = fmaf(x.z, y.z, dacc);
        dacc = fmaf(x.w, y.w, dacc);
        tacc += (y.x + y.y) + (y.z + y.w);

        // local max of the 4; rescale only when it beats the running max
        // (short predicated arm, ~1 exp per element total)
        float lm = fmaxf(fmaxf(x.x, x.y), fmaxf(x.z, x.w));
        if (lm > m) {
            s *= __expf(m - lm);   // first hit: s==0, __expf(-inf)=0 -> stays 0
            m = lm;
        }
        s += __expf(x.x - m) + __expf(x.y - m)
           + __expf(x.z - m) + __expf(x.w - m);
    }

    // ---- warp reduction of (m, s, dacc, tacc) ----
    #pragma unroll
    for (int off = 16; off > 0; off >>= 1) {
        float m2 = __shfl_xor_sync(0xFFFFFFFFu, m, off);
        float s2 = __shfl_xor_sync(0xFFFFFFFFu, s, off);
        float nm = fmaxf(m, m2);
        s = s * __expf(m - nm) + s2 * __expf(m2 - nm);
        m = nm;
        dacc += __shfl_xor_sync(0xFFFFFFFFu, dacc, off);
        tacc += __shfl_xor_sync(0xFFFFFFFFu, tacc, off);
    }

    // ---- block reduction across warps ----
    __shared__ float sh_m[NWARPS], sh_s[NWARPS], sh_d[NWARPS], sh_t[NWARPS];
    const int wid = tid >> 5;
    const int lid = tid & 31;
    if (lid == 0) {
        sh_m[wid] = m; sh_s[wid] = s; sh_d[wid] = dacc; sh_t[wid] = tacc;
    }
    __syncthreads();

    if (tid == 0) {
        float M = sh_m[0], S = sh_s[0], D = sh_d[0], T = sh_t[0];
        #pragma unroll
        for (int w = 1; w < NWARPS; w++) {
            float m2 = sh_m[w], s2 = sh_s[w];
            float nm = fmaxf(M, m2);
            S = S * __expf(M - nm) + s2 * __expf(m2 - nm);
            M = nm;
            D += sh_d[w];
            T += sh_t[w];
        }
        float lse = M + __logf(S);
        // one global atomic per CTA; kernel boundary orders it vs finalize
        atomicAdd(&g_sum, lse * T - D);
    }
}

__global__ void ce_finalize_kernel(float* __restrict__ out)
{
    out[0] = g_sum * (1.0f / (float)N_ROWS);
    g_sum  = 0.0f;   // reset for next graph replay
}

extern "C" void kernel_launch(void* const* d_in, const int* in_sizes, int n_in,
                              void* d_out, int out_size)
{
    const float* pred = (const float*)d_in[0];
    const float* tgt  = (const float*)d_in[1];
    float* out = (float*)d_out;

    ce_row_kernel<<<N_ROWS, THREADS>>>(pred, tgt);
    ce_finalize_kernel<<<1, 1>>>(out);
}